// round 15
// baseline (speedup 1.0000x reference)
#include <cuda_runtime.h>
#include <math.h>

#define E    384
#define EE   (E * E)           // 147456 columns
#define TC   32                // columns per block (one warp-width)
#define NBLK (EE / TC)         // 4608 blocks
#define RG   12                // row groups (= warps per block)
#define KPT  (E / RG)          // 32 rows per thread, register-resident
#define THREADS (TC * RG)      // 384

// Order-preserving uint staging for per-row max of (t - lse).
// Zero at module load; gm_fin re-zeros after each read (graph-replay safe).
__device__ unsigned g_stage[E];

__device__ __forceinline__ unsigned fkey(float f) {
    unsigned u = __float_as_uint(f);
    return (u & 0x80000000u) ? ~u : (u | 0x80000000u);
}
__device__ __forceinline__ float funkey(unsigned k) {
    return __uint_as_float((k & 0x80000000u) ? (k ^ 0x80000000u) : ~k);
}

__global__ void __launch_bounds__(THREADS, 2)
gm_main(const float* __restrict__ x,
        const float* __restrict__ kern,
        const float* __restrict__ bias,
        const float* __restrict__ space)
{
    __shared__ float x_s[E];
    __shared__ float red[RG][TC];            // cross-warp column-sum reduction
    __shared__ float tr[RG][KPT][TC + 1];    // warp-private transpose tiles

    const int tid = threadIdx.x;
    const int cid = tid & 31;       // lane = column within tile
    const int rg  = tid >> 5;       // warp = row group
    const int k0  = rg * KPT;

    const int c = blockIdx.x * TC + cid;   // global column
    const int l = c % E;                   // kron diag index
    const int j = c / E;

    // Warp-local x staging: pass A only reads this warp's 32 rows, so no
    // block-wide barrier is needed before streaming starts.
    x_s[k0 + cid] = x[k0 + cid];
    __syncwarp();

    const float INV_SQRT2 = 0.70710678118654752440f;
    // Diagonal kernel term: only live where row k == l; owned by one warp.
    // x[j] via direct L2-broadcast load (outside the hot loop).
    float dval = 0.0f;
    if (l >= k0 && l < k0 + KPT)
        dval = kern[(size_t)l * EE + c] * __ldg(&x[j]) * INV_SQRT2;

    // Pass A: stream space+bias, build t in registers, accumulate exp-sum.
    // 85-reg budget (384 thr x 2 blocks) -> deep front-batched load window.
    // |t| <= ~1 for this layer's scaling, so no max-shift is needed.
    float v[KPT];
    float s_local = 0.0f;
    const size_t base = (size_t)k0 * EE + (size_t)c;
    #pragma unroll
    for (int kk = 0; kk < KPT; ++kk) {
        const int k = k0 + kk;
        const size_t idx = base + (size_t)kk * EE;
        float t = space[idx] + bias[idx];
        if (k == l) t += dval;
        t *= x_s[k];
        v[kk] = t;
        s_local += __expf(t);
    }

    // Column exp-sum across the 12 row-group warps -> logsumexp.
    red[rg][cid] = s_local;
    __syncthreads();
    float s_c = red[0][cid];
    #pragma unroll
    for (int r = 1; r < RG; ++r) s_c += red[r][cid];
    const float lse = __logf(s_c);

    // Pass C (warp-local): transpose (t - lse) through smem, then all 32
    // lanes each take the max of one row across 32 columns (full warp).
    #pragma unroll
    for (int kk = 0; kk < KPT; ++kk)
        tr[rg][kk][cid] = v[kk] - lse;
    __syncwarp();
    {
        float best = tr[rg][cid][0];
        #pragma unroll
        for (int cc = 1; cc < TC; ++cc)
            best = fmaxf(best, tr[rg][cid][cc]);
        atomicMax(&g_stage[k0 + cid], fkey(best));   // REDG, coalesced 128B
    }
}

// out[k] = exp(max); then re-zero staging for the next graph replay.
// PDL: scheduled during gm_main's tail; griddepsync gates on completion
// (implicit trigger at grid end -> g_stage atomics are visible).
__global__ void gm_fin(float* __restrict__ out) {
    cudaGridDependencySynchronize();
    const int k = threadIdx.x;
    out[k] = __expf(funkey(g_stage[k]));
    g_stage[k] = 0u;
}

extern "C" void kernel_launch(void* const* d_in, const int* in_sizes, int n_in,
                              void* d_out, int out_size)
{
    const float* x     = (const float*)d_in[0];
    const float* kern  = (const float*)d_in[1];
    const float* bias  = (const float*)d_in[2];
    const float* space = (const float*)d_in[3];
    float* out = (float*)d_out;

    gm_main<<<NBLK, THREADS>>>(x, kern, bias, space);

    cudaLaunchConfig_t cfg = {};
    cfg.gridDim  = dim3(1, 1, 1);
    cfg.blockDim = dim3(E, 1, 1);
    cudaLaunchAttribute attr[1];
    attr[0].id = cudaLaunchAttributeProgrammaticStreamSerialization;
    attr[0].val.programmaticStreamSerializationAllowed = 1;
    cfg.attrs = attr;
    cfg.numAttrs = 1;
    cudaLaunchKernelEx(&cfg, gm_fin, out);
}

// round 16
// speedup vs baseline: 1.0489x; 1.0489x over previous
#include <cuda_runtime.h>
#include <math.h>

#define E    384
#define EE   (E * E)           // 147456 columns
#define TC   32                // columns per block (one warp-width)
#define NBLK (EE / TC)         // 4608 blocks
#define RG   16                // row groups (= warps per block)
#define KPT  (E / RG)          // 24 rows per thread, register-resident
#define THREADS (TC * RG)      // 512

// Order-preserving uint staging for per-row max of (t - lse).
// Zero at module load; gm_fin re-zeros after each read (graph-replay safe).
__device__ unsigned g_stage[E];

__device__ __forceinline__ unsigned fkey(float f) {
    unsigned u = __float_as_uint(f);
    return (u & 0x80000000u) ? ~u : (u | 0x80000000u);
}
__device__ __forceinline__ float funkey(unsigned k) {
    return __uint_as_float((k & 0x80000000u) ? (k ^ 0x80000000u) : ~k);
}

__global__ void __launch_bounds__(THREADS, 2)
gm_main(const float* __restrict__ x,
        const float* __restrict__ kern,
        const float* __restrict__ bias,
        const float* __restrict__ space)
{
    __shared__ float x_s[E];
    __shared__ float red[RG][TC];            // cross-warp column-sum reduction
    __shared__ float tr[RG][KPT][TC + 1];    // warp-private transpose tiles

    const int tid = threadIdx.x;
    const int cid = tid & 31;       // lane = column within tile
    const int rg  = tid >> 5;       // warp = row group
    const int k0  = rg * KPT;

    const int c = blockIdx.x * TC + cid;   // global column
    const int l = c % E;                   // kron diag index
    const int j = c / E;

    // Warp-local x staging: pass A only reads this warp's 24 rows, so no
    // block-wide barrier is needed before streaming starts.
    if (cid < KPT) x_s[k0 + cid] = x[k0 + cid];
    __syncwarp();

    const float INV_SQRT2 = 0.70710678118654752440f;
    // Diagonal kernel term: only live where row k == l; owned by one warp.
    // x[j] via direct L2-broadcast load (outside the hot loop).
    float dval = 0.0f;
    if (l >= k0 && l < k0 + KPT)
        dval = kern[(size_t)l * EE + c] * __ldg(&x[j]) * INV_SQRT2;

    // Pass A: stream space+bias, build t in registers, accumulate exp-sum.
    // |t| <= ~1 for this layer's scaling, so no max-shift is needed.
    float v[KPT];
    float s_local = 0.0f;
    const size_t base = (size_t)k0 * EE + (size_t)c;
    #pragma unroll
    for (int kk = 0; kk < KPT; ++kk) {
        const int k = k0 + kk;
        const size_t idx = base + (size_t)kk * EE;
        float t = space[idx] + bias[idx];
        if (k == l) t += dval;
        t *= x_s[k];
        v[kk] = t;
        s_local += __expf(t);
    }

    // Column exp-sum across the 16 row-group warps -> logsumexp.
    red[rg][cid] = s_local;
    __syncthreads();
    float s_c = red[0][cid];
    #pragma unroll
    for (int r = 1; r < RG; ++r) s_c += red[r][cid];
    const float lse = __logf(s_c);

    // Pass C (warp-local): transpose (t - lse) through smem, then
    // lanes 0..23 each take the max of one row across 32 columns.
    #pragma unroll
    for (int kk = 0; kk < KPT; ++kk)
        tr[rg][kk][cid] = v[kk] - lse;
    __syncwarp();
    if (cid < KPT) {
        float best = tr[rg][cid][0];
        #pragma unroll
        for (int cc = 1; cc < TC; ++cc)
            best = fmaxf(best, tr[rg][cid][cc]);
        atomicMax(&g_stage[k0 + cid], fkey(best));   // REDG, spread addrs
    }
}

// out[k] = exp(max); then re-zero staging for the next graph replay.
// PDL: scheduled during gm_main's tail; griddepsync gates on completion
// (implicit trigger at grid end -> g_stage atomics are visible).
__global__ void gm_fin(float* __restrict__ out) {
    cudaGridDependencySynchronize();
    const int k = threadIdx.x;
    out[k] = __expf(funkey(g_stage[k]));
    g_stage[k] = 0u;
}

extern "C" void kernel_launch(void* const* d_in, const int* in_sizes, int n_in,
                              void* d_out, int out_size)
{
    const float* x     = (const float*)d_in[0];
    const float* kern  = (const float*)d_in[1];
    const float* bias  = (const float*)d_in[2];
    const float* space = (const float*)d_in[3];
    float* out = (float*)d_out;

    gm_main<<<NBLK, THREADS>>>(x, kern, bias, space);

    cudaLaunchConfig_t cfg = {};
    cfg.gridDim  = dim3(1, 1, 1);
    cfg.blockDim = dim3(E, 1, 1);
    cudaLaunchAttribute attr[1];
    attr[0].id = cudaLaunchAttributeProgrammaticStreamSerialization;
    attr[0].val.programmaticStreamSerializationAllowed = 1;
    cfg.attrs = attr;
    cfg.numAttrs = 1;
    cudaLaunchKernelEx(&cfg, gm_fin, out);
}